// round 5
// baseline (speedup 1.0000x reference)
#include <cuda_runtime.h>
#include <cuda_bf16.h>
#include <cstdint>

#define N_ROWS   16384
#define DIN      128
#define DOUT     64
#define KDIM     16384
#define MIN_NORM 1e-15f
#define ART_CLAMP (1.0f - 1e-7f)
#define MAXNORM  (1.0f - 4e-3f)

#define MTILE   64
#define TKSUP   128                 // k per super-iteration (64 per warp k-half)
#define NIT     (KDIM / TKSUP)      // 128
#define BPITCH  144                 // B smem row pitch (conflict-free ldmatrix)
#define BTILE   (64 * BPITCH)       // 9216 B per n64 x k64 tile
#define STAGEB  (4 * BTILE)         // [hi_k0, lo_k0, hi_k1, lo_k1] = 36864
#define BSTAGES 3
#define SMEM_BYTES (BSTAGES * STAGEB)   // 110592

// Pre-split, pre-transposed tangent matrix: [DOUT][KDIM] K-major bf16
__device__ __nv_bfloat16 g_Bhi[DOUT * KDIM];
__device__ __nv_bfloat16 g_Blo[DOUT * KDIM];

// ---------------------------------------------------------------------------
// helpers
// ---------------------------------------------------------------------------
__device__ __forceinline__ uint32_t smem_u32(const void* p) {
    uint32_t a;
    asm("{ .reg .u64 t; cvta.to.shared.u64 t, %1; cvt.u32.u64 %0, t; }" : "=r"(a) : "l"(p));
    return a;
}
__device__ __forceinline__ uint32_t cvt_bf16x2(float lo, float hi) {
    uint32_t r;
    asm("cvt.rn.bf16x2.f32 %0, %1, %2;" : "=r"(r) : "f"(hi), "f"(lo));
    return r;
}
__device__ __forceinline__ void cp_async16(uint32_t dst, const void* src) {
    asm volatile(
        "{ .reg .u64 gp; cvta.to.global.u64 gp, %1;"
        " cp.async.cg.shared.global [%0], [gp], 16; }"
        :: "r"(dst), "l"(src) : "memory");
}
#define CP_COMMIT()  asm volatile("cp.async.commit_group;" ::: "memory")
#define CP_WAIT1()   asm volatile("cp.async.wait_group 1;" ::: "memory")
#define CP_WAIT0()   asm volatile("cp.async.wait_group 0;" ::: "memory")

__device__ __forceinline__ void ldsm4(uint32_t addr, uint32_t* r) {
    asm volatile("ldmatrix.sync.aligned.m8n8.x4.shared.b16 {%0,%1,%2,%3}, [%4];"
                 : "=r"(r[0]), "=r"(r[1]), "=r"(r[2]), "=r"(r[3]) : "r"(addr));
}
__device__ __forceinline__ void mma_bf16(float* c, const uint32_t* a,
                                         uint32_t b0, uint32_t b1) {
    asm volatile(
        "mma.sync.aligned.m16n8k16.row.col.f32.bf16.bf16.f32 "
        "{%0,%1,%2,%3}, {%4,%5,%6,%7}, {%8,%9}, {%0,%1,%2,%3};"
        : "+f"(c[0]), "+f"(c[1]), "+f"(c[2]), "+f"(c[3])
        : "r"(a[0]), "r"(a[1]), "r"(a[2]), "r"(a[3]), "r"(b0), "r"(b1));
}
__device__ __forceinline__ float wsum(float v) {
#pragma unroll
    for (int o = 16; o > 0; o >>= 1) v += __shfl_xor_sync(0xffffffffu, v, o);
    return v;
}

// ---------------------------------------------------------------------------
// Kernel A: hyperbolic transform -> tangent -> bf16 hi/lo, K-major transposed.
// Warp-per-row; all reductions via shfl. (unchanged from R4)
// ---------------------------------------------------------------------------
__global__ __launch_bounds__(256) void transform_kernel(
    const float* __restrict__ X,
    const float* __restrict__ W,
    const float* __restrict__ bias)
{
    __shared__ float2 sW2[DIN * 32];   // [k][t] = (W[k][t], W[k][t+32])

    const int tid = threadIdx.x;
    for (int i = tid; i < DIN * 32; i += 256) {
        const int k = i >> 5, t = i & 31;
        sW2[i] = make_float2(W[k * DOUT + t], W[k * DOUT + t + 32]);
    }
    __syncthreads();

    const int w    = tid >> 5;
    const int lane = tid & 31;
    const int row  = blockIdx.x * 8 + w;

    // hyp_bias = proj(expmap0(bias))
    float b1 = bias[lane], b2v = bias[lane + 32];
    float b2 = wsum(b1 * b1 + b2v * b2v);
    float bn = fmaxf(sqrtf(b2), MIN_NORM);
    float tb = tanhf(bn) / bn;
    float e1 = tb * b1, e2v = tb * b2v;
    float e2 = wsum(e1 * e1 + e2v * e2v);
    float en = fmaxf(sqrtf(e2), MIN_NORM);
    float sc = (en > MAXNORM) ? (MAXNORM / en) : 1.f;
    float h1 = e1 * sc, h2v = e2v * sc;
    float h2 = wsum(h1 * h1 + h2v * h2v);

    float xr[4];
#pragma unroll
    for (int j = 0; j < 4; ++j) xr[j] = X[(size_t)row * DIN + lane + 32 * j];
    float x2 = wsum(xr[0] * xr[0] + xr[1] * xr[1] + xr[2] * xr[2] + xr[3] * xr[3]);

    float ma = 0.f, mb = 0.f;
#pragma unroll
    for (int j = 0; j < 4; ++j) {
#pragma unroll
        for (int l = 0; l < 32; ++l) {
            const float xv = __shfl_sync(0xffffffffu, xr[j], l);
            const float2 wv = sW2[(j * 32 + l) * 32 + lane];
            ma = fmaf(xv, wv.x, ma);
            mb = fmaf(xv, wv.y, mb);
        }
    }

    float m2 = wsum(ma * ma + mb * mb);
    float xn = fmaxf(sqrtf(x2), MIN_NORM);
    float mn = fmaxf(sqrtf(m2), MIN_NORM);

    float artx = atanhf(fminf(xn, ART_CLAMP));
    float tf   = tanhf(mn / xn * artx) / mn;
    float r1 = tf * ma, r2v = tf * mb;
    if (m2 == 0.f) { r1 = 0.f; r2v = 0.f; }

    float r2 = wsum(r1 * r1 + r2v * r2v);
    float rh = wsum(r1 * h1 + r2v * h2v);
    float al  = 1.f + 2.f * rh + h2;
    float den = fmaxf(1.f + 2.f * rh + r2 * h2, MIN_NORM);
    float p1  = (al * r1  + (1.f - r2) * h1)  / den;
    float p2v = (al * r2v + (1.f - r2) * h2v) / den;

    float p2 = wsum(p1 * p1 + p2v * p2v);
    float pn = fmaxf(sqrtf(p2), MIN_NORM);
    if (pn > MAXNORM) {
        float s = MAXNORM / pn;
        p1 *= s; p2v *= s; pn = MAXNORM;
    }

    float lf = atanhf(fminf(pn, ART_CLAMP)) / pn;
    float t1 = lf * p1, t2 = lf * p2v;

    __nv_bfloat16 h1b = __float2bfloat16(t1);
    __nv_bfloat16 h2b = __float2bfloat16(t2);
    g_Bhi[(size_t)lane * KDIM + row]        = h1b;
    g_Bhi[(size_t)(lane + 32) * KDIM + row] = h2b;
    g_Blo[(size_t)lane * KDIM + row]        = __float2bfloat16(t1 - __bfloat162float(h1b));
    g_Blo[(size_t)(lane + 32) * KDIM + row] = __float2bfloat16(t2 - __bfloat162float(h2b));
}

// ---------------------------------------------------------------------------
// Kernel B: out = relu(A @ T) via mma.sync bf16-split.
// 256 CTAs (M64) x 256 thr, forced 2 CTAs/SM (16 warps/SM).
// 8 warps = 4 m-groups x 2 k-halves; k-half partials reduced via smem.
// B: 3-stage cp.async, 4 tiles/stage. A: LDG at iter top, cvt in regs.
// ---------------------------------------------------------------------------
__global__ __launch_bounds__(256, 2) void gemm_kernel(
    const float* __restrict__ A,
    float* __restrict__ out)
{
    extern __shared__ __align__(128) char sB[];   // [stage][hi0|lo0|hi1|lo1]

    const int tid   = threadIdx.x;
    const int w     = tid >> 5;
    const int lane  = tid & 31;
    const int g     = lane >> 2;
    const int t4    = lane & 3;
    const int mg    = w & 3;        // m-group 0..3
    const int khalf = w >> 2;       // 0 or 1
    const int m0    = blockIdx.x * MTILE;

    // A pointers for this warp's rows / k-half
    const float* pa0 = A + (size_t)(m0 + mg * 16 + g) * KDIM + khalf * 64 + 2 * t4;
    const float* pa8 = pa0 + (size_t)8 * KDIM;

    // cp.async mapping: 8 x 16B per thread per stage
    //   j in 0..7: tile = j>>1, row = 32*(j&1) + (tid>>3), q = tid&7
    const int brow = tid >> 3;
    const int q    = tid & 7;
    const uint32_t sb0 = smem_u32(sB);
    uint32_t cpDst[8];
    const __nv_bfloat16* cpSrc[8];
#pragma unroll
    for (int j = 0; j < 8; ++j) {
        const int tile = j >> 1;
        const int row  = 32 * (j & 1) + brow;
        cpDst[j] = (uint32_t)(tile * BTILE + row * BPITCH + q * 16);
        const __nv_bfloat16* arr = (tile & 1) ? g_Blo : g_Bhi;
        cpSrc[j] = arr + (size_t)row * KDIM + (tile >> 1) * 64 + q * 8;
    }

    // ldmatrix lane offset within a tile
    const uint32_t lmOff = (uint32_t)((lane & 7) * BPITCH + (lane >> 3) * 16);

    float acc[8][4];
#pragma unroll
    for (int i = 0; i < 8; ++i)
#pragma unroll
        for (int j = 0; j < 4; ++j) acc[i][j] = 0.f;

    // prologue: B stages 0,1
#pragma unroll
    for (int s = 0; s < 2; ++s) {
        const int kb = s * TKSUP;
        const uint32_t db = sb0 + (uint32_t)(s * STAGEB);
#pragma unroll
        for (int j = 0; j < 8; ++j) cp_async16(db + cpDst[j], cpSrc[j] + kb);
        CP_COMMIT();
    }

    for (int i = 0; i < NIT; ++i) {
        const int s = i % BSTAGES;

        if (i < NIT - 1) { CP_WAIT1(); } else { CP_WAIT0(); }
        __syncthreads();

        // issue stage i+2 (slot consumed at iter i-1; sync above makes it safe)
        if (i + 2 < NIT) {
            const int kb = (i + 2) * TKSUP;
            const uint32_t db = sb0 + (uint32_t)(((i + 2) % BSTAGES) * STAGEB);
#pragma unroll
            for (int j = 0; j < 8; ++j) cp_async16(db + cpDst[j], cpSrc[j] + kb);
            CP_COMMIT();
        }

        // load + convert this iter's A (k64 slice for this warp's k-half)
        const int kb = i * TKSUP;
        float2 av[16];
#pragma unroll
        for (int kf = 0; kf < 4; ++kf) {
            av[kf * 4 + 0] = *(const float2*)(pa0 + kb + kf * 16);
            av[kf * 4 + 1] = *(const float2*)(pa0 + kb + kf * 16 + 8);
            av[kf * 4 + 2] = *(const float2*)(pa8 + kb + kf * 16);
            av[kf * 4 + 3] = *(const float2*)(pa8 + kb + kf * 16 + 8);
        }
        uint32_t ahF[16], alF[16];
        {
            const int map[4] = {0, 2, 1, 3};
#pragma unroll
            for (int kf = 0; kf < 4; ++kf) {
#pragma unroll
                for (int j = 0; j < 4; ++j) {
                    const float2 v = av[kf * 4 + map[j]];
                    const uint32_t h = cvt_bf16x2(v.x, v.y);
                    const float lx = v.x - __uint_as_float(h << 16);
                    const float ly = v.y - __uint_as_float(h & 0xFFFF0000u);
                    ahF[kf * 4 + j] = h;
                    alF[kf * 4 + j] = cvt_bf16x2(lx, ly);
                }
            }
        }

        const uint32_t bhBase = sb0 + (uint32_t)(s * STAGEB + khalf * 2 * BTILE) + lmOff;
        const uint32_t blBase = bhBase + BTILE;

#pragma unroll
        for (int p = 0; p < 2; ++p) {
            const uint32_t* ah0 = ahF + (2 * p) * 4;
            const uint32_t* ah1 = ahF + (2 * p + 1) * 4;
            const uint32_t* al0 = alF + (2 * p) * 4;
            const uint32_t* al1 = alF + (2 * p + 1) * 4;
            const uint32_t pOff = (uint32_t)(p * 64);

            uint32_t bf[8][4];
            // hi tile: all ldsm first, then nt-major passes (acc reuse distance 8)
#pragma unroll
            for (int nt = 0; nt < 8; ++nt)
                ldsm4(bhBase + (uint32_t)(nt * 8 * BPITCH) + pOff, bf[nt]);
#pragma unroll
            for (int nt = 0; nt < 8; ++nt) mma_bf16(acc[nt], ah0, bf[nt][0], bf[nt][1]);
#pragma unroll
            for (int nt = 0; nt < 8; ++nt) mma_bf16(acc[nt], al0, bf[nt][0], bf[nt][1]);
#pragma unroll
            for (int nt = 0; nt < 8; ++nt) mma_bf16(acc[nt], ah1, bf[nt][2], bf[nt][3]);
#pragma unroll
            for (int nt = 0; nt < 8; ++nt) mma_bf16(acc[nt], al1, bf[nt][2], bf[nt][3]);
            // lo tile
#pragma unroll
            for (int nt = 0; nt < 8; ++nt)
                ldsm4(blBase + (uint32_t)(nt * 8 * BPITCH) + pOff, bf[nt]);
#pragma unroll
            for (int nt = 0; nt < 8; ++nt) mma_bf16(acc[nt], ah0, bf[nt][0], bf[nt][1]);
#pragma unroll
            for (int nt = 0; nt < 8; ++nt) mma_bf16(acc[nt], ah1, bf[nt][2], bf[nt][3]);
        }
    }

    // k-half reduction via smem (reuse B stages), then relu + store
    __syncthreads();
    float* red = (float*)sB;
    if (khalf == 1) {
        float* dst = red + (size_t)mg * 1024 + lane * 32;
#pragma unroll
        for (int nt = 0; nt < 8; ++nt) {
#pragma unroll
            for (int j = 0; j < 4; ++j) dst[nt * 4 + j] = acc[nt][j];
        }
    }
    __syncthreads();
    if (khalf == 0) {
        const float* src = red + (size_t)mg * 1024 + lane * 32;
        const int rowTop = m0 + mg * 16 + g;
#pragma unroll
        for (int nt = 0; nt < 8; ++nt) {
            const int col = nt * 8 + t4 * 2;
            float2 v0 = make_float2(fmaxf(acc[nt][0] + src[nt * 4 + 0], 0.f),
                                    fmaxf(acc[nt][1] + src[nt * 4 + 1], 0.f));
            float2 v1 = make_float2(fmaxf(acc[nt][2] + src[nt * 4 + 2], 0.f),
                                    fmaxf(acc[nt][3] + src[nt * 4 + 3], 0.f));
            *(float2*)(out + (size_t)rowTop * DOUT + col)       = v0;
            *(float2*)(out + (size_t)(rowTop + 8) * DOUT + col) = v1;
        }
    }
}

// ---------------------------------------------------------------------------
extern "C" void kernel_launch(void* const* d_in, const int* in_sizes, int n_in,
                              void* d_out, int out_size)
{
    const float* adj  = (const float*)d_in[0];   // [16384, 16384]
    const float* x    = (const float*)d_in[1];   // [16384, 128]
    const float* w    = (const float*)d_in[2];   // [128, 64]
    const float* bias = (const float*)d_in[3];   // [64]
    float* out = (float*)d_out;                  // [16384, 64]

    cudaFuncSetAttribute(gemm_kernel, cudaFuncAttributeMaxDynamicSharedMemorySize, SMEM_BYTES);

    transform_kernel<<<N_ROWS / 8, 256>>>(x, w, bias);
    gemm_kernel<<<N_ROWS / MTILE, 256, SMEM_BYTES>>>(adj, out);
}

// round 6
// speedup vs baseline: 1.0865x; 1.0865x over previous
#include <cuda_runtime.h>
#include <cuda_bf16.h>
#include <cstdint>

#define N_ROWS   16384
#define DIN      128
#define DOUT     64
#define KDIM     16384
#define MIN_NORM 1e-15f
#define ART_CLAMP (1.0f - 1e-7f)
#define MAXNORM  (1.0f - 4e-3f)

#define TK      64            // k per chunk
#define NCH     (KDIM / TK)   // 256 chunks
#define BPITCH  144           // B smem row pitch (conflict-free ldmatrix)
#define BTILE   (64 * BPITCH) // 9216 B per (hi|lo) tile
#define BSTAGES 3
#define SMEM_B_BYTES (BSTAGES * 2 * BTILE)   // 55296

// Pre-split, pre-transposed tangent matrix: [DOUT][KDIM] K-major bf16
__device__ __nv_bfloat16 g_Bhi[DOUT * KDIM];
__device__ __nv_bfloat16 g_Blo[DOUT * KDIM];

// ---------------------------------------------------------------------------
// helpers
// ---------------------------------------------------------------------------
__device__ __forceinline__ uint32_t smem_u32(const void* p) {
    uint32_t a;
    asm("{ .reg .u64 t; cvta.to.shared.u64 t, %1; cvt.u32.u64 %0, t; }" : "=r"(a) : "l"(p));
    return a;
}
__device__ __forceinline__ uint32_t cvt_bf16x2(float lo, float hi) {
    uint32_t r;
    asm("cvt.rn.bf16x2.f32 %0, %1, %2;" : "=r"(r) : "f"(hi), "f"(lo));
    return r;
}
__device__ __forceinline__ void cp_async16(uint32_t dst, const void* src) {
    asm volatile(
        "{ .reg .u64 gp; cvta.to.global.u64 gp, %1;"
        " cp.async.cg.shared.global [%0], [gp], 16; }"
        :: "r"(dst), "l"(src) : "memory");
}
#define CP_COMMIT()  asm volatile("cp.async.commit_group;" ::: "memory")
#define CP_WAIT1()   asm volatile("cp.async.wait_group 1;" ::: "memory")
#define CP_WAIT0()   asm volatile("cp.async.wait_group 0;" ::: "memory")

__device__ __forceinline__ void ldsm4(uint32_t addr, uint32_t* r) {
    asm volatile("ldmatrix.sync.aligned.m8n8.x4.shared.b16 {%0,%1,%2,%3}, [%4];"
                 : "=r"(r[0]), "=r"(r[1]), "=r"(r[2]), "=r"(r[3]) : "r"(addr));
}
__device__ __forceinline__ void mma_bf16(float* c, const uint32_t* a,
                                         uint32_t b0, uint32_t b1) {
    asm volatile(
        "mma.sync.aligned.m16n8k16.row.col.f32.bf16.bf16.f32 "
        "{%0,%1,%2,%3}, {%4,%5,%6,%7}, {%8,%9}, {%0,%1,%2,%3};"
        : "+f"(c[0]), "+f"(c[1]), "+f"(c[2]), "+f"(c[3])
        : "r"(a[0]), "r"(a[1]), "r"(a[2]), "r"(a[3]), "r"(b0), "r"(b1));
}
__device__ __forceinline__ float wsum(float v) {
#pragma unroll
    for (int o = 16; o > 0; o >>= 1) v += __shfl_xor_sync(0xffffffffu, v, o);
    return v;
}

// ---------------------------------------------------------------------------
// Kernel A: hyperbolic transform -> tangent -> bf16 hi/lo, K-major transposed.
// ---------------------------------------------------------------------------
__global__ __launch_bounds__(256) void transform_kernel(
    const float* __restrict__ X,
    const float* __restrict__ W,
    const float* __restrict__ bias)
{
    __shared__ float2 sW2[DIN * 32];   // [k][t] = (W[k][t], W[k][t+32])

    const int tid = threadIdx.x;
    for (int i = tid; i < DIN * 32; i += 256) {
        const int k = i >> 5, t = i & 31;
        sW2[i] = make_float2(W[k * DOUT + t], W[k * DOUT + t + 32]);
    }
    __syncthreads();

    const int w    = tid >> 5;
    const int lane = tid & 31;
    const int row  = blockIdx.x * 8 + w;

    // hyp_bias = proj(expmap0(bias))
    float b1 = bias[lane], b2v = bias[lane + 32];
    float b2 = wsum(b1 * b1 + b2v * b2v);
    float bn = fmaxf(sqrtf(b2), MIN_NORM);
    float tb = tanhf(bn) / bn;
    float e1 = tb * b1, e2v = tb * b2v;
    float e2 = wsum(e1 * e1 + e2v * e2v);
    float en = fmaxf(sqrtf(e2), MIN_NORM);
    float sc = (en > MAXNORM) ? (MAXNORM / en) : 1.f;
    float h1 = e1 * sc, h2v = e2v * sc;
    float h2 = wsum(h1 * h1 + h2v * h2v);

    float xr[4];
#pragma unroll
    for (int j = 0; j < 4; ++j) xr[j] = X[(size_t)row * DIN + lane + 32 * j];
    float x2 = wsum(xr[0] * xr[0] + xr[1] * xr[1] + xr[2] * xr[2] + xr[3] * xr[3]);

    float ma = 0.f, mb = 0.f;
#pragma unroll
    for (int j = 0; j < 4; ++j) {
#pragma unroll
        for (int l = 0; l < 32; ++l) {
            const float xv = __shfl_sync(0xffffffffu, xr[j], l);
            const float2 wv = sW2[(j * 32 + l) * 32 + lane];
            ma = fmaf(xv, wv.x, ma);
            mb = fmaf(xv, wv.y, mb);
        }
    }

    float m2 = wsum(ma * ma + mb * mb);
    float xn = fmaxf(sqrtf(x2), MIN_NORM);
    float mn = fmaxf(sqrtf(m2), MIN_NORM);

    float artx = atanhf(fminf(xn, ART_CLAMP));
    float tf   = tanhf(mn / xn * artx) / mn;
    float r1 = tf * ma, r2v = tf * mb;
    if (m2 == 0.f) { r1 = 0.f; r2v = 0.f; }

    float r2 = wsum(r1 * r1 + r2v * r2v);
    float rh = wsum(r1 * h1 + r2v * h2v);
    float al  = 1.f + 2.f * rh + h2;
    float den = fmaxf(1.f + 2.f * rh + r2 * h2, MIN_NORM);
    float p1  = (al * r1  + (1.f - r2) * h1)  / den;
    float p2v = (al * r2v + (1.f - r2) * h2v) / den;

    float p2 = wsum(p1 * p1 + p2v * p2v);
    float pn = fmaxf(sqrtf(p2), MIN_NORM);
    if (pn > MAXNORM) {
        float s = MAXNORM / pn;
        p1 *= s; p2v *= s; pn = MAXNORM;
    }

    float lf = atanhf(fminf(pn, ART_CLAMP)) / pn;
    float t1 = lf * p1, t2 = lf * p2v;

    __nv_bfloat16 h1b = __float2bfloat16(t1);
    __nv_bfloat16 h2b = __float2bfloat16(t2);
    g_Bhi[(size_t)lane * KDIM + row]        = h1b;
    g_Bhi[(size_t)(lane + 32) * KDIM + row] = h2b;
    g_Blo[(size_t)lane * KDIM + row]        = __float2bfloat16(t1 - __bfloat162float(h1b));
    g_Blo[(size_t)(lane + 32) * KDIM + row] = __float2bfloat16(t2 - __bfloat162float(h2b));
}

// ---------------------------------------------------------------------------
// Kernel B: out = relu(A @ T) via mma.sync bf16-split.
// 128 CTAs x 256 thr; warp m16 x n64; K-chunk 64.
// A: LDG -> regs (cross-iteration prefetch) -> cvt overlapped with cp-wait.
// B: 3-stage cp.async; fragment double-buffer across 4 quads per chunk.
// ---------------------------------------------------------------------------
struct APre { float2 v[16]; };

__device__ __forceinline__ void ldA(APre& p, const float* pa0, const float* pa8, int kb) {
#pragma unroll
    for (int kf = 0; kf < 4; ++kf) {
        p.v[kf * 4 + 0] = *(const float2*)(pa0 + kb + kf * 16);
        p.v[kf * 4 + 1] = *(const float2*)(pa0 + kb + kf * 16 + 8);
        p.v[kf * 4 + 2] = *(const float2*)(pa8 + kb + kf * 16);
        p.v[kf * 4 + 3] = *(const float2*)(pa8 + kb + kf * 16 + 8);
    }
}

// mma fragment order: a0=(g,c0) a1=(g+8,c0) a2=(g,c0+8) a3=(g+8,c0+8)
__device__ __forceinline__ void cvtA(const APre& p, uint32_t* ah, uint32_t* al) {
    const int map[4] = {0, 2, 1, 3};
#pragma unroll
    for (int kf = 0; kf < 4; ++kf) {
#pragma unroll
        for (int j = 0; j < 4; ++j) {
            const float2 v = p.v[kf * 4 + map[j]];
            const uint32_t h = cvt_bf16x2(v.x, v.y);
            const float lx = v.x - __uint_as_float(h << 16);
            const float ly = v.y - __uint_as_float(h & 0xFFFF0000u);
            ah[kf * 4 + j] = h;
            al[kf * 4 + j] = cvt_bf16x2(lx, ly);
        }
    }
}

__global__ __launch_bounds__(256, 1) void gemm_kernel(
    const float* __restrict__ A,
    float* __restrict__ out)
{
    extern __shared__ __align__(128) char sB[];   // [stage][hi/lo][64 * BPITCH]

    const int tid  = threadIdx.x;
    const int w    = tid >> 5;
    const int lane = tid & 31;
    const int g    = lane >> 2;
    const int t4   = lane & 3;
    const int m0   = blockIdx.x * 128;

    const float* pa0 = A + (size_t)(m0 + w * 16 + g) * KDIM + 2 * t4;
    const float* pa8 = pa0 + (size_t)8 * KDIM;

    // B cp.async mapping: 4 x 16B per thread per stage
    const int n0 = tid >> 3, q0 = tid & 7;
    const int n1 = (tid + 256) >> 3, q1 = tid & 7;
    const uint32_t sb0 = smem_u32(sB);
    const uint32_t dOff0 = (uint32_t)(n0 * BPITCH + q0 * 16);
    const uint32_t dOff1 = (uint32_t)(n1 * BPITCH + q1 * 16);
    const __nv_bfloat16* srcH0 = &g_Bhi[(size_t)n0 * KDIM + q0 * 8];
    const __nv_bfloat16* srcH1 = &g_Bhi[(size_t)n1 * KDIM + q1 * 8];
    const __nv_bfloat16* srcL0 = &g_Blo[(size_t)n0 * KDIM + q0 * 8];
    const __nv_bfloat16* srcL1 = &g_Blo[(size_t)n1 * KDIM + q1 * 8];

    // ldmatrix lane offset
    const uint32_t lmOff = (uint32_t)((lane & 7) * BPITCH + (lane >> 3) * 16);

    float accA[8][4], accB[8][4];
#pragma unroll
    for (int i = 0; i < 8; ++i)
#pragma unroll
        for (int j = 0; j < 4; ++j) { accA[i][j] = 0.f; accB[i][j] = 0.f; }

    // prologue: B stages 0,1 ; A chunk 0
#pragma unroll
    for (int s = 0; s < 2; ++s) {
        const int kb = s * TK;
        const uint32_t db = sb0 + (uint32_t)(s * 2 * BTILE);
        cp_async16(db + dOff0,         srcH0 + kb);
        cp_async16(db + dOff1,         srcH1 + kb);
        cp_async16(db + BTILE + dOff0, srcL0 + kb);
        cp_async16(db + BTILE + dOff1, srcL1 + kb);
        CP_COMMIT();
    }

    APre pre;
    ldA(pre, pa0, pa8, 0);

    uint32_t ahF[16], alF[16];
    uint32_t bf[2][8][4];

    for (int i = 0; i < NCH; ++i) {
        const int s = i % BSTAGES;

        // convert A chunk i from regs loaded last iteration (overlaps cp-wait)
        cvtA(pre, ahF, alF);

        if (i < NCH - 1) { CP_WAIT1(); } else { CP_WAIT0(); }
        __syncthreads();

        const uint32_t bhBase = sb0 + (uint32_t)(s * 2 * BTILE) + lmOff;
        const uint32_t blBase = bhBase + BTILE;

        // quad 0 fragments (p0, hi) — first LDSM batch of the chunk
#pragma unroll
        for (int nt = 0; nt < 8; ++nt)
            ldsm4(bhBase + (uint32_t)(nt * 8 * BPITCH), bf[0][nt]);

        // issue B stage i+2 (slot consumed at chunk i-1; barrier above makes it safe)
        if (i + 2 < NCH) {
            const int kb = (i + 2) * TK;
            const uint32_t db = sb0 + (uint32_t)(((i + 2) % BSTAGES) * 2 * BTILE);
            cp_async16(db + dOff0,         srcH0 + kb);
            cp_async16(db + dOff1,         srcH1 + kb);
            cp_async16(db + BTILE + dOff0, srcL0 + kb);
            cp_async16(db + BTILE + dOff1, srcL1 + kb);
            CP_COMMIT();
        }

        // prefetch A chunk i+1 (full-chunk latency window)
        if (i + 1 < NCH) ldA(pre, pa0, pa8, (i + 1) * TK);

        // 4 quads: (p0,hi) (p0,lo) (p1,hi) (p1,lo); ldsm[q+1] before MMA[q]
#pragma unroll
        for (int q = 0; q < 4; ++q) {
            const int p   = q >> 1;
            const int cb  = q & 1;             // current frag buffer
            // prefetch next quad's fragments
            if (q < 3) {
                const int qn = q + 1;
                const uint32_t nb = ((qn & 1) ? blBase : bhBase) + (uint32_t)((qn >> 1) * 64);
#pragma unroll
                for (int nt = 0; nt < 8; ++nt)
                    ldsm4(nb + (uint32_t)(nt * 8 * BPITCH), bf[cb ^ 1][nt]);
            }
            const uint32_t* ah0 = ahF + (2 * p) * 4;
            const uint32_t* ah1 = ahF + (2 * p + 1) * 4;
            const uint32_t* al0 = alF + (2 * p) * 4;
            const uint32_t* al1 = alF + (2 * p + 1) * 4;
            uint32_t (*bq)[4] = bf[cb];

            if ((q & 1) == 0) {   // hi tile: 32 MMAs
#pragma unroll
                for (int nt = 0; nt < 8; ++nt) mma_bf16(accA[nt], ah0, bq[nt][0], bq[nt][1]);
#pragma unroll
                for (int nt = 0; nt < 8; ++nt) mma_bf16(accB[nt], al0, bq[nt][0], bq[nt][1]);
#pragma unroll
                for (int nt = 0; nt < 8; ++nt) mma_bf16(accA[nt], ah1, bq[nt][2], bq[nt][3]);
#pragma unroll
                for (int nt = 0; nt < 8; ++nt) mma_bf16(accB[nt], al1, bq[nt][2], bq[nt][3]);
            } else {              // lo tile: 16 MMAs
#pragma unroll
                for (int nt = 0; nt < 8; ++nt) mma_bf16(accA[nt], ah0, bq[nt][0], bq[nt][1]);
#pragma unroll
                for (int nt = 0; nt < 8; ++nt) mma_bf16(accB[nt], ah1, bq[nt][2], bq[nt][3]);
            }
        }
    }

    // epilogue: relu(accA+accB)
    const int rowTop = m0 + w * 16 + g;
#pragma unroll
    for (int nt = 0; nt < 8; ++nt) {
        const int col = nt * 8 + t4 * 2;
        float2 v0 = make_float2(fmaxf(accA[nt][0] + accB[nt][0], 0.f),
                                fmaxf(accA[nt][1] + accB[nt][1], 0.f));
        float2 v1 = make_float2(fmaxf(accA[nt][2] + accB[nt][2], 0.f),
                                fmaxf(accA[nt][3] + accB[nt][3], 0.f));
        *(float2*)(out + (size_t)rowTop * DOUT + col)       = v0;
        *(float2*)(out + (size_t)(rowTop + 8) * DOUT + col) = v1;
    }
}

// ---------------------------------------------------------------------------
extern "C" void kernel_launch(void* const* d_in, const int* in_sizes, int n_in,
                              void* d_out, int out_size)
{
    const float* adj  = (const float*)d_in[0];   // [16384, 16384]
    const float* x    = (const float*)d_in[1];   // [16384, 128]
    const float* w    = (const float*)d_in[2];   // [128, 64]
    const float* bias = (const float*)d_in[3];   // [64]
    float* out = (float*)d_out;                  // [16384, 64]

    cudaFuncSetAttribute(gemm_kernel, cudaFuncAttributeMaxDynamicSharedMemorySize, SMEM_B_BYTES);

    transform_kernel<<<N_ROWS / 8, 256>>>(x, w, bias);
    gemm_kernel<<<N_ROWS / 128, 256, SMEM_B_BYTES>>>(adj, out);
}

// round 7
// speedup vs baseline: 1.1975x; 1.1022x over previous
#include <cuda_runtime.h>
#include <cuda_bf16.h>
#include <cstdint>

#define N_ROWS   16384
#define DIN      128
#define DOUT     64
#define KDIM     16384
#define MIN_NORM 1e-15f
#define ART_CLAMP (1.0f - 1e-7f)
#define MAXNORM  (1.0f - 4e-3f)

#define TK      64            // k per chunk
#define NCH     (KDIM / TK)   // 256 chunks
#define BPITCH  144           // B smem row pitch (conflict-free ldmatrix)
#define BTILE   (64 * BPITCH) // 9216 B per (hi|lo) tile
#define BSTAGES 3
#define SMEM_B_BYTES (BSTAGES * 2 * BTILE)   // 55296

// Pre-split, pre-transposed tangent matrix: [DOUT][KDIM] K-major bf16
__device__ __nv_bfloat16 g_Bhi[DOUT * KDIM];
__device__ __nv_bfloat16 g_Blo[DOUT * KDIM];

// ---------------------------------------------------------------------------
// helpers
// ---------------------------------------------------------------------------
__device__ __forceinline__ uint32_t smem_u32(const void* p) {
    uint32_t a;
    asm("{ .reg .u64 t; cvta.to.shared.u64 t, %1; cvt.u32.u64 %0, t; }" : "=r"(a) : "l"(p));
    return a;
}
__device__ __forceinline__ uint32_t cvt_bf16x2(float lo, float hi) {
    uint32_t r;
    asm("cvt.rn.bf16x2.f32 %0, %1, %2;" : "=r"(r) : "f"(hi), "f"(lo));
    return r;
}
__device__ __forceinline__ void cp_async16(uint32_t dst, const void* src) {
    asm volatile(
        "{ .reg .u64 gp; cvta.to.global.u64 gp, %1;"
        " cp.async.cg.shared.global [%0], [gp], 16; }"
        :: "r"(dst), "l"(src) : "memory");
}
#define CP_COMMIT()  asm volatile("cp.async.commit_group;" ::: "memory")
#define CP_WAIT1()   asm volatile("cp.async.wait_group 1;" ::: "memory")
#define CP_WAIT0()   asm volatile("cp.async.wait_group 0;" ::: "memory")

__device__ __forceinline__ void ldsm4(uint32_t addr, uint32_t* r) {
    asm volatile("ldmatrix.sync.aligned.m8n8.x4.shared.b16 {%0,%1,%2,%3}, [%4];"
                 : "=r"(r[0]), "=r"(r[1]), "=r"(r[2]), "=r"(r[3]) : "r"(addr));
}
__device__ __forceinline__ void mma_bf16(float* c, const uint32_t* a,
                                         uint32_t b0, uint32_t b1) {
    asm volatile(
        "mma.sync.aligned.m16n8k16.row.col.f32.bf16.bf16.f32 "
        "{%0,%1,%2,%3}, {%4,%5,%6,%7}, {%8,%9}, {%0,%1,%2,%3};"
        : "+f"(c[0]), "+f"(c[1]), "+f"(c[2]), "+f"(c[3])
        : "r"(a[0]), "r"(a[1]), "r"(a[2]), "r"(a[3]), "r"(b0), "r"(b1));
}
__device__ __forceinline__ float wsum(float v) {
#pragma unroll
    for (int o = 16; o > 0; o >>= 1) v += __shfl_xor_sync(0xffffffffu, v, o);
    return v;
}

// ---------------------------------------------------------------------------
// Kernel A: hyperbolic transform -> tangent -> bf16 hi/lo, K-major transposed.
// (unchanged — proven)
// ---------------------------------------------------------------------------
__global__ __launch_bounds__(256) void transform_kernel(
    const float* __restrict__ X,
    const float* __restrict__ W,
    const float* __restrict__ bias)
{
    __shared__ float2 sW2[DIN * 32];   // [k][t] = (W[k][t], W[k][t+32])

    const int tid = threadIdx.x;
    for (int i = tid; i < DIN * 32; i += 256) {
        const int k = i >> 5, t = i & 31;
        sW2[i] = make_float2(W[k * DOUT + t], W[k * DOUT + t + 32]);
    }
    __syncthreads();

    const int w    = tid >> 5;
    const int lane = tid & 31;
    const int row  = blockIdx.x * 8 + w;

    // hyp_bias = proj(expmap0(bias))
    float b1 = bias[lane], b2v = bias[lane + 32];
    float b2 = wsum(b1 * b1 + b2v * b2v);
    float bn = fmaxf(sqrtf(b2), MIN_NORM);
    float tb = tanhf(bn) / bn;
    float e1 = tb * b1, e2v = tb * b2v;
    float e2 = wsum(e1 * e1 + e2v * e2v);
    float en = fmaxf(sqrtf(e2), MIN_NORM);
    float sc = (en > MAXNORM) ? (MAXNORM / en) : 1.f;
    float h1 = e1 * sc, h2v = e2v * sc;
    float h2 = wsum(h1 * h1 + h2v * h2v);

    float xr[4];
#pragma unroll
    for (int j = 0; j < 4; ++j) xr[j] = X[(size_t)row * DIN + lane + 32 * j];
    float x2 = wsum(xr[0] * xr[0] + xr[1] * xr[1] + xr[2] * xr[2] + xr[3] * xr[3]);

    float ma = 0.f, mb = 0.f;
#pragma unroll
    for (int j = 0; j < 4; ++j) {
#pragma unroll
        for (int l = 0; l < 32; ++l) {
            const float xv = __shfl_sync(0xffffffffu, xr[j], l);
            const float2 wv = sW2[(j * 32 + l) * 32 + lane];
            ma = fmaf(xv, wv.x, ma);
            mb = fmaf(xv, wv.y, mb);
        }
    }

    float m2 = wsum(ma * ma + mb * mb);
    float xn = fmaxf(sqrtf(x2), MIN_NORM);
    float mn = fmaxf(sqrtf(m2), MIN_NORM);

    float artx = atanhf(fminf(xn, ART_CLAMP));
    float tf   = tanhf(mn / xn * artx) / mn;
    float r1 = tf * ma, r2v = tf * mb;
    if (m2 == 0.f) { r1 = 0.f; r2v = 0.f; }

    float r2 = wsum(r1 * r1 + r2v * r2v);
    float rh = wsum(r1 * h1 + r2v * h2v);
    float al  = 1.f + 2.f * rh + h2;
    float den = fmaxf(1.f + 2.f * rh + r2 * h2, MIN_NORM);
    float p1  = (al * r1  + (1.f - r2) * h1)  / den;
    float p2v = (al * r2v + (1.f - r2) * h2v) / den;

    float p2 = wsum(p1 * p1 + p2v * p2v);
    float pn = fmaxf(sqrtf(p2), MIN_NORM);
    if (pn > MAXNORM) {
        float s = MAXNORM / pn;
        p1 *= s; p2v *= s; pn = MAXNORM;
    }

    float lf = atanhf(fminf(pn, ART_CLAMP)) / pn;
    float t1 = lf * p1, t2 = lf * p2v;

    __nv_bfloat16 h1b = __float2bfloat16(t1);
    __nv_bfloat16 h2b = __float2bfloat16(t2);
    g_Bhi[(size_t)lane * KDIM + row]        = h1b;
    g_Bhi[(size_t)(lane + 32) * KDIM + row] = h2b;
    g_Blo[(size_t)lane * KDIM + row]        = __float2bfloat16(t1 - __bfloat162float(h1b));
    g_Blo[(size_t)(lane + 32) * KDIM + row] = __float2bfloat16(t2 - __bfloat162float(h2b));
}

// ---------------------------------------------------------------------------
// Kernel B: out = relu(A @ T) via mma.sync bf16-split.
// 128 CTAs x 512 thr (16 warps = 8 m-groups x 2 k-halves), M128/N64/K-chunk 64.
// Same pipeline order as R4; per-warp k32 halves the register footprint so
// 16 warps fit (4 warps/SMSP). k-half partials reduced via smem at epilogue.
// ---------------------------------------------------------------------------
struct APre { float2 v[8]; };   // k32 slice: kf in {0,1}

__device__ __forceinline__ void ldA(APre& p, const float* pa0, const float* pa8, int kb) {
#pragma unroll
    for (int kf = 0; kf < 2; ++kf) {
        p.v[kf * 4 + 0] = *(const float2*)(pa0 + kb + kf * 16);
        p.v[kf * 4 + 1] = *(const float2*)(pa0 + kb + kf * 16 + 8);
        p.v[kf * 4 + 2] = *(const float2*)(pa8 + kb + kf * 16);
        p.v[kf * 4 + 3] = *(const float2*)(pa8 + kb + kf * 16 + 8);
    }
}

// mma fragment order: a0=(g,c0) a1=(g+8,c0) a2=(g,c0+8) a3=(g+8,c0+8)
__device__ __forceinline__ void cvtA(const APre& p, uint32_t* ah, uint32_t* al) {
    const int map[4] = {0, 2, 1, 3};
#pragma unroll
    for (int kf = 0; kf < 2; ++kf) {
#pragma unroll
        for (int j = 0; j < 4; ++j) {
            const float2 v = p.v[kf * 4 + map[j]];
            const uint32_t h = cvt_bf16x2(v.x, v.y);
            const float lx = v.x - __uint_as_float(h << 16);
            const float ly = v.y - __uint_as_float(h & 0xFFFF0000u);
            ah[kf * 4 + j] = h;
            al[kf * 4 + j] = cvt_bf16x2(lx, ly);
        }
    }
}

__global__ __launch_bounds__(512, 1) void gemm_kernel(
    const float* __restrict__ A,
    float* __restrict__ out)
{
    extern __shared__ __align__(128) char sB[];   // [stage][hi/lo][64 * BPITCH]

    const int tid   = threadIdx.x;
    const int w     = tid >> 5;
    const int lane  = tid & 31;
    const int g     = lane >> 2;
    const int t4    = lane & 3;
    const int mg    = w >> 1;       // m-group 0..7
    const int khalf = w & 1;        // k-half of each chunk
    const int m0    = blockIdx.x * 128;

    // A pointers: rows m0 + mg*16 + g (+8); this warp's k32 within each chunk
    const float* pa0 = A + (size_t)(m0 + mg * 16 + g) * KDIM + khalf * 32 + 2 * t4;
    const float* pa8 = pa0 + (size_t)8 * KDIM;

    // B cp.async mapping: 2 x 16B per thread per stage
    //   idx = tid      -> hi tile, row tid>>3, q tid&7
    //   idx = tid+512  -> lo tile, same row/q
    const int brow = tid >> 3;
    const int q    = tid & 7;
    const uint32_t sb0 = smem_u32(sB);
    const uint32_t dOffH = (uint32_t)(brow * BPITCH + q * 16);
    const uint32_t dOffL = dOffH + (uint32_t)BTILE;
    const __nv_bfloat16* srcH = &g_Bhi[(size_t)brow * KDIM + q * 8];
    const __nv_bfloat16* srcL = &g_Blo[(size_t)brow * KDIM + q * 8];

    // ldmatrix lane offset within a tile (+ khalf selects k32)
    const uint32_t lmOff = (uint32_t)((lane & 7) * BPITCH + (lane >> 3) * 16 + khalf * 64);

    float acc[8][4];
#pragma unroll
    for (int i = 0; i < 8; ++i)
#pragma unroll
        for (int j = 0; j < 4; ++j) acc[i][j] = 0.f;

    // prologue: B stages 0,1 ; A chunk 0
#pragma unroll
    for (int s = 0; s < 2; ++s) {
        const int kb = s * TK;
        const uint32_t db = sb0 + (uint32_t)(s * 2 * BTILE);
        cp_async16(db + dOffH, srcH + kb);
        cp_async16(db + dOffL, srcL + kb);
        CP_COMMIT();
    }

    APre pre;
    ldA(pre, pa0, pa8, 0);

    uint32_t ahF[8], alF[8];
    uint32_t bf[8][4];

    for (int i = 0; i < NCH; ++i) {
        const int s = i % BSTAGES;

        if (i < NCH - 1) { CP_WAIT1(); } else { CP_WAIT0(); }
        __syncthreads();

        // issue B stage i+2 (slot consumed at chunk i-1; barrier above makes it safe)
        if (i + 2 < NCH) {
            const int kb = (i + 2) * TK;
            const uint32_t db = sb0 + (uint32_t)(((i + 2) % BSTAGES) * 2 * BTILE);
            cp_async16(db + dOffH, srcH + kb);
            cp_async16(db + dOffL, srcL + kb);
            CP_COMMIT();
        }

        // convert A chunk i (regs loaded last iter), then prefetch chunk i+1
        cvtA(pre, ahF, alF);
        if (i + 1 < NCH) ldA(pre, pa0, pa8, (i + 1) * TK);

        const uint32_t bhBase = sb0 + (uint32_t)(s * 2 * BTILE) + lmOff;
        const uint32_t blBase = bhBase + BTILE;

        const uint32_t* ah0 = ahF;
        const uint32_t* ah1 = ahF + 4;
        const uint32_t* al0 = alF;
        const uint32_t* al1 = alF + 4;

        // hi tile: all ldsm first, then nt-major bursts (acc reuse distance 8)
#pragma unroll
        for (int nt = 0; nt < 8; ++nt)
            ldsm4(bhBase + (uint32_t)(nt * 8 * BPITCH), bf[nt]);
#pragma unroll
        for (int nt = 0; nt < 8; ++nt) mma_bf16(acc[nt], ah0, bf[nt][0], bf[nt][1]);
#pragma unroll
        for (int nt = 0; nt < 8; ++nt) mma_bf16(acc[nt], al0, bf[nt][0], bf[nt][1]);
#pragma unroll
        for (int nt = 0; nt < 8; ++nt) mma_bf16(acc[nt], ah1, bf[nt][2], bf[nt][3]);
#pragma unroll
        for (int nt = 0; nt < 8; ++nt) mma_bf16(acc[nt], al1, bf[nt][2], bf[nt][3]);
        // lo tile
#pragma unroll
        for (int nt = 0; nt < 8; ++nt)
            ldsm4(blBase + (uint32_t)(nt * 8 * BPITCH), bf[nt]);
#pragma unroll
        for (int nt = 0; nt < 8; ++nt) mma_bf16(acc[nt], ah0, bf[nt][0], bf[nt][1]);
#pragma unroll
        for (int nt = 0; nt < 8; ++nt) mma_bf16(acc[nt], ah1, bf[nt][2], bf[nt][3]);
    }

    // k-half reduction via smem (reuses B buffers), then relu + store
    __syncthreads();
    float* red = (float*)sB;
    if (khalf == 1) {
        float* dst = red + (size_t)mg * 1024 + lane * 32;
#pragma unroll
        for (int nt = 0; nt < 8; ++nt)
#pragma unroll
            for (int j = 0; j < 4; ++j) dst[nt * 4 + j] = acc[nt][j];
    }
    __syncthreads();
    if (khalf == 0) {
        const float* src = red + (size_t)mg * 1024 + lane * 32;
        const int rowTop = m0 + mg * 16 + g;
#pragma unroll
        for (int nt = 0; nt < 8; ++nt) {
            const int col = nt * 8 + t4 * 2;
            float2 v0 = make_float2(fmaxf(acc[nt][0] + src[nt * 4 + 0], 0.f),
                                    fmaxf(acc[nt][1] + src[nt * 4 + 1], 0.f));
            float2 v1 = make_float2(fmaxf(acc[nt][2] + src[nt * 4 + 2], 0.f),
                                    fmaxf(acc[nt][3] + src[nt * 4 + 3], 0.f));
            *(float2*)(out + (size_t)rowTop * DOUT + col)       = v0;
            *(float2*)(out + (size_t)(rowTop + 8) * DOUT + col) = v1;
        }
    }
}

// ---------------------------------------------------------------------------
extern "C" void kernel_launch(void* const* d_in, const int* in_sizes, int n_in,
                              void* d_out, int out_size)
{
    const float* adj  = (const float*)d_in[0];   // [16384, 16384]
    const float* x    = (const float*)d_in[1];   // [16384, 128]
    const float* w    = (const float*)d_in[2];   // [128, 64]
    const float* bias = (const float*)d_in[3];   // [64]
    float* out = (float*)d_out;                  // [16384, 64]

    cudaFuncSetAttribute(gemm_kernel, cudaFuncAttributeMaxDynamicSharedMemorySize, SMEM_B_BYTES);

    transform_kernel<<<N_ROWS / 8, 256>>>(x, w, bias);
    gemm_kernel<<<N_ROWS / 128, 512, SMEM_B_BYTES>>>(adj, out);
}